// round 1
// baseline (speedup 1.0000x reference)
#include <cuda_runtime.h>
#include <cuda_bf16.h>
#include <cstdint>
#include <math.h>

#define DI __device__ __forceinline__

static constexpr int B_DIM = 8;
static constexpr int SEQ   = 1024;
static constexpr int CH    = 768;
static constexpr int NH    = 12;
static constexpr int HD    = 64;
static constexpr int HID   = 3072;
static constexpr int ROWS  = B_DIM * SEQ;   // 8192
static constexpr int BH    = B_DIM * NH;    // 96

// ---------------- scratch: device globals (no runtime allocation) ------------
__device__ __nv_bfloat16 g_h1[ROWS * CH];
__device__ __nv_bfloat16 g_h2[ROWS * CH];
__device__ __nv_bfloat16 g_wqkvT[3 * CH * CH];
__device__ __nv_bfloat16 g_wprojT[CH * CH];
__device__ __nv_bfloat16 g_w1T[HID * CH];
__device__ __nv_bfloat16 g_w2T[CH * HID];
__device__ __nv_bfloat16 g_q[BH * SEQ * HD];
__device__ __nv_bfloat16 g_k[BH * SEQ * HD];
__device__ __nv_bfloat16 g_vT[BH * HD * SEQ];
__device__ __nv_bfloat16 g_S[(size_t)BH * SEQ * SEQ];
__device__ __nv_bfloat16 g_P[(size_t)BH * SEQ * SEQ];
__device__ __nv_bfloat16 g_attn[ROWS * CH];
__device__ float         g_x1[ROWS * CH];
__device__ __nv_bfloat16 g_mid[(size_t)ROWS * HID];

// ---------------- small helper kernels ---------------------------------------

// out[n][k] = bf16(in[k][n])   (in is [K][Nc] row-major fp32)
__global__ void transpose_bf16(const float* __restrict__ in,
                               __nv_bfloat16* __restrict__ out, int K, int Nc) {
    int idx = blockIdx.x * 256 + threadIdx.x;
    if (idx >= K * Nc) return;
    int k = idx / Nc, n = idx - k * Nc;
    out[(size_t)n * K + k] = __float2bfloat16(in[idx]);
}

// LayerNorm over CH=768, one block (256 thr) per row, fp32 in -> bf16 out
__global__ void ln_kernel(const float* __restrict__ x, const float* __restrict__ g,
                          const float* __restrict__ b, __nv_bfloat16* __restrict__ out) {
    int row = blockIdx.x;
    const float* xr = x + (size_t)row * CH;
    int t = threadIdx.x;
    float v0 = xr[t], v1 = xr[t + 256], v2 = xr[t + 512];
    float s  = v0 + v1 + v2;
    float s2 = v0 * v0 + v1 * v1 + v2 * v2;
#pragma unroll
    for (int o = 16; o; o >>= 1) {
        s  += __shfl_xor_sync(0xffffffffu, s,  o);
        s2 += __shfl_xor_sync(0xffffffffu, s2, o);
    }
    __shared__ float sh[16];
    int w = t >> 5, l = t & 31;
    if (l == 0) { sh[w] = s; sh[w + 8] = s2; }
    __syncthreads();
    float ts = 0.f, ts2 = 0.f;
#pragma unroll
    for (int i = 0; i < 8; i++) { ts += sh[i]; ts2 += sh[i + 8]; }
    float mu  = ts * (1.f / CH);
    float var = ts2 * (1.f / CH) - mu * mu;
    float inv = rsqrtf(var + 1e-5f);
    __nv_bfloat16* orow = out + (size_t)row * CH;
    orow[t]       = __float2bfloat16((v0 - mu) * inv * g[t]       + b[t]);
    orow[t + 256] = __float2bfloat16((v1 - mu) * inv * g[t + 256] + b[t + 256]);
    orow[t + 512] = __float2bfloat16((v2 - mu) * inv * g[t + 512] + b[t + 512]);
}

// Row softmax over SEQ=1024, one block (256 thr) per row. bf16 -> bf16
__global__ void softmax_kernel(const __nv_bfloat16* __restrict__ S,
                               __nv_bfloat16* __restrict__ P) {
    size_t row = blockIdx.x;
    const __nv_bfloat16* sr = S + row * SEQ;
    __nv_bfloat16* pr = P + row * SEQ;
    int t = threadIdx.x;
    const __nv_bfloat162* sp = reinterpret_cast<const __nv_bfloat162*>(sr) + t * 2;
    __nv_bfloat162 p0 = sp[0], p1 = sp[1];
    float v[4];
    v[0] = __bfloat162float(p0.x); v[1] = __bfloat162float(p0.y);
    v[2] = __bfloat162float(p1.x); v[3] = __bfloat162float(p1.y);

    float m = fmaxf(fmaxf(v[0], v[1]), fmaxf(v[2], v[3]));
#pragma unroll
    for (int o = 16; o; o >>= 1) m = fmaxf(m, __shfl_xor_sync(0xffffffffu, m, o));
    __shared__ float sh[8];
    int w = t >> 5, l = t & 31;
    if (l == 0) sh[w] = m;
    __syncthreads();
    float bm = sh[0];
#pragma unroll
    for (int i = 1; i < 8; i++) bm = fmaxf(bm, sh[i]);

    float e[4], sum = 0.f;
#pragma unroll
    for (int j = 0; j < 4; j++) { e[j] = __expf(v[j] - bm); sum += e[j]; }
#pragma unroll
    for (int o = 16; o; o >>= 1) sum += __shfl_xor_sync(0xffffffffu, sum, o);
    __syncthreads();
    if (l == 0) sh[w] = sum;
    __syncthreads();
    float bs = 0.f;
#pragma unroll
    for (int i = 0; i < 8; i++) bs += sh[i];
    float r = 1.f / bs;

    __nv_bfloat162* pp = reinterpret_cast<__nv_bfloat162*>(pr) + t * 2;
    pp[0] = __nv_bfloat162(__float2bfloat16(e[0] * r), __float2bfloat16(e[1] * r));
    pp[1] = __nv_bfloat162(__float2bfloat16(e[2] * r), __float2bfloat16(e[3] * r));
}

// ---------------- bf16 mma.sync GEMM (NT: C = A[M,K] * B[Nn,K]^T) -------------

DI void mma_bf16(float* c, const uint32_t* a, const uint32_t* b) {
    asm volatile(
        "mma.sync.aligned.m16n8k16.row.col.f32.bf16.bf16.f32 "
        "{%0,%1,%2,%3}, {%4,%5,%6,%7}, {%8,%9}, {%0,%1,%2,%3};\n"
        : "+f"(c[0]), "+f"(c[1]), "+f"(c[2]), "+f"(c[3])
        : "r"(a[0]), "r"(a[1]), "r"(a[2]), "r"(a[3]), "r"(b[0]), "r"(b[1]));
}

template <int BM, int BN, class Epi>
__global__ void __launch_bounds__(256)
gemm_nt(const __nv_bfloat16* __restrict__ A, const __nv_bfloat16* __restrict__ Bm,
        int K, long long strideA, long long strideB, Epi epi) {
    constexpr int BK = 32;
    constexpr int WARPS_M = 4, WARPS_N = 2;
    constexpr int WM = BM / WARPS_M;          // 32
    constexpr int WN = BN / WARPS_N;          // 64 (BN=128) / 32 (BN=64)
    constexpr int MT = WM / 16;               // 2
    constexpr int NT = WN / 8;                // 8 / 4
    constexpr int LDS = 20;                   // words per smem row (40 bf16, padded)

    __shared__ __align__(16) uint32_t As[BM * LDS];
    __shared__ __align__(16) uint32_t Bs[BN * LDS];

    int bat = blockIdx.z;
    const __nv_bfloat16* Ab = A  + (size_t)bat * strideA;
    const __nv_bfloat16* Bb = Bm + (size_t)bat * strideB;
    int rowBase = blockIdx.x * BM, colBase = blockIdx.y * BN;
    int tid = threadIdx.x, lane = tid & 31, warp = tid >> 5;
    int wm = warp / WARPS_N, wn = warp % WARPS_N;
    int g = lane >> 2, ct = lane & 3;

    float acc[MT][NT][4];
#pragma unroll
    for (int i = 0; i < MT; i++)
#pragma unroll
        for (int j = 0; j < NT; j++)
#pragma unroll
            for (int q = 0; q < 4; q++) acc[i][j][q] = 0.f;

    constexpr int ALD = BM * BK / 8 / 256;    // 2
    constexpr int BLD = BN * BK / 8 / 256;    // 2 / 1

    for (int kt = 0; kt < K; kt += BK) {
#pragma unroll
        for (int i = 0; i < ALD; i++) {
            int idx = tid + i * 256;
            int r = idx >> 2, cg = idx & 3;
            uint4 val = *reinterpret_cast<const uint4*>(
                Ab + (size_t)(rowBase + r) * K + kt + cg * 8);
            *reinterpret_cast<uint4*>(&As[r * LDS + cg * 4]) = val;
        }
#pragma unroll
        for (int i = 0; i < BLD; i++) {
            int idx = tid + i * 256;
            int r = idx >> 2, cg = idx & 3;
            uint4 val = *reinterpret_cast<const uint4*>(
                Bb + (size_t)(colBase + r) * K + kt + cg * 8);
            *reinterpret_cast<uint4*>(&Bs[r * LDS + cg * 4]) = val;
        }
        __syncthreads();
#pragma unroll
        for (int kk = 0; kk < 2; kk++) {
            uint32_t af[MT][4], bf[NT][2];
#pragma unroll
            for (int mt = 0; mt < MT; mt++) {
                int r0 = (wm * WM + mt * 16 + g) * LDS + kk * 8 + ct;
                af[mt][0] = As[r0];
                af[mt][1] = As[r0 + 8 * LDS];
                af[mt][2] = As[r0 + 4];
                af[mt][3] = As[r0 + 8 * LDS + 4];
            }
#pragma unroll
            for (int nt = 0; nt < NT; nt++) {
                int r0 = (wn * WN + nt * 8 + g) * LDS + kk * 8 + ct;
                bf[nt][0] = Bs[r0];
                bf[nt][1] = Bs[r0 + 4];
            }
#pragma unroll
            for (int mt = 0; mt < MT; mt++)
#pragma unroll
                for (int nt = 0; nt < NT; nt++)
                    mma_bf16(acc[mt][nt], af[mt], bf[nt]);
        }
        __syncthreads();
    }

#pragma unroll
    for (int mt = 0; mt < MT; mt++)
#pragma unroll
        for (int nt = 0; nt < NT; nt++) {
            int r = rowBase + wm * WM + mt * 16 + g;
            int c = colBase + wn * WN + nt * 8 + ct * 2;
            epi(r,     c,     bat, acc[mt][nt][0]);
            epi(r,     c + 1, bat, acc[mt][nt][1]);
            epi(r + 8, c,     bat, acc[mt][nt][2]);
            epi(r + 8, c + 1, bat, acc[mt][nt][3]);
        }
}

// ---------------- epilogues ---------------------------------------------------

struct EpiQKV {  // scatter qkv GEMM output into q / k / v^T head layouts
    __nv_bfloat16 *q, *k, *vT;
    DI void operator()(int r, int c, int, float v) const {
        int s = c / CH;
        int rem = c - s * CH;
        int h = rem >> 6, d = rem & 63;
        int b = r >> 10, n = r & 1023;
        int bh = b * NH + h;
        __nv_bfloat16 bv = __float2bfloat16(v);
        if (s == 0)      q [((size_t)bh * SEQ + n) * HD + d] = bv;
        else if (s == 1) k [((size_t)bh * SEQ + n) * HD + d] = bv;
        else             vT[((size_t)bh * HD  + d) * SEQ + n] = bv;
    }
};

struct EpiScores {  // S = v*exp(temp[h]) + lw[h]*loc(n,m)
    __nv_bfloat16* S;
    const float* temp;
    const float* lw;
    DI void operator()(int n, int m, int bh, float v) const {
        int h = bh % NH;
        float scale = __expf(__ldg(temp + h));
        float yi = (float)(n >> 5) * (1.f / 31.f), xi = (float)(n & 31) * (1.f / 31.f);
        float yj = (float)(m >> 5) * (1.f / 31.f), xj = (float)(m & 31) * (1.f / 31.f);
        float dy = yi - yj, dx = xi - xj;
        float loc = -0.5f * (dy * dy + dx * dx);   // max d2 == 2.0 exactly
        S[((size_t)bh * SEQ + n) * SEQ + m] =
            __float2bfloat16(v * scale + __ldg(lw + h) * loc);
    }
};

struct EpiAV {  // gather heads back to [B*SEQ, CH]
    __nv_bfloat16* attn;
    DI void operator()(int n, int d, int bh, float v) const {
        int b = bh / NH, h = bh % NH;
        attn[((size_t)(b * SEQ + n)) * CH + h * HD + d] = __float2bfloat16(v);
    }
};

struct EpiResid {  // out = base + (v + bias[c]) * ls[c]   (fp32)
    const float* base;
    const float* bias;
    const float* ls;
    float* out;
    DI void operator()(int r, int c, int, float v) const {
        size_t i = (size_t)r * CH + c;
        out[i] = base[i] + (v + __ldg(bias + c)) * __ldg(ls + c);
    }
};

struct EpiGelu {  // exact gelu(v + bias) -> bf16
    const float* bias;
    __nv_bfloat16* out;
    DI void operator()(int r, int c, int, float v) const {
        float t = v + __ldg(bias + c);
        float gl = 0.5f * t * (1.f + erff(t * 0.70710678118654752f));
        out[(size_t)r * HID + c] = __float2bfloat16(gl);
    }
};

// ---------------- launch ------------------------------------------------------

extern "C" void kernel_launch(void* const* d_in, const int* in_sizes, int n_in,
                              void* d_out, int out_size) {
    (void)in_sizes; (void)n_in; (void)out_size;
    const float* x      = (const float*)d_in[0];
    const float* w_qkv  = (const float*)d_in[1];
    const float* w_proj = (const float*)d_in[2];
    const float* b_proj = (const float*)d_in[3];
    const float* ln1_g  = (const float*)d_in[4];
    const float* ln1_b  = (const float*)d_in[5];
    const float* ln2_g  = (const float*)d_in[6];
    const float* ln2_b  = (const float*)d_in[7];
    const float* temp   = (const float*)d_in[8];
    const float* lw     = (const float*)d_in[9];
    const float* ls1    = (const float*)d_in[10];
    const float* ls2    = (const float*)d_in[11];
    const float* w1     = (const float*)d_in[12];
    const float* b1     = (const float*)d_in[13];
    const float* w2     = (const float*)d_in[14];
    const float* b2     = (const float*)d_in[15];
    float* out = (float*)d_out;

    __nv_bfloat16 *p_h1, *p_h2, *p_wqkvT, *p_wprojT, *p_w1T, *p_w2T;
    __nv_bfloat16 *p_q, *p_k, *p_vT, *p_S, *p_P, *p_attn, *p_mid;
    float* p_x1;
    cudaGetSymbolAddress((void**)&p_h1, g_h1);
    cudaGetSymbolAddress((void**)&p_h2, g_h2);
    cudaGetSymbolAddress((void**)&p_wqkvT, g_wqkvT);
    cudaGetSymbolAddress((void**)&p_wprojT, g_wprojT);
    cudaGetSymbolAddress((void**)&p_w1T, g_w1T);
    cudaGetSymbolAddress((void**)&p_w2T, g_w2T);
    cudaGetSymbolAddress((void**)&p_q, g_q);
    cudaGetSymbolAddress((void**)&p_k, g_k);
    cudaGetSymbolAddress((void**)&p_vT, g_vT);
    cudaGetSymbolAddress((void**)&p_S, g_S);
    cudaGetSymbolAddress((void**)&p_P, g_P);
    cudaGetSymbolAddress((void**)&p_attn, g_attn);
    cudaGetSymbolAddress((void**)&p_x1, g_x1);
    cudaGetSymbolAddress((void**)&p_mid, g_mid);

    // weight transposes (fp32 -> bf16, [K][N] -> [N][K])
    transpose_bf16<<<(CH * 3 * CH + 255) / 256, 256>>>(w_qkv, p_wqkvT, CH, 3 * CH);
    transpose_bf16<<<(CH * CH + 255) / 256, 256>>>(w_proj, p_wprojT, CH, CH);
    transpose_bf16<<<(CH * HID + 255) / 256, 256>>>(w1, p_w1T, CH, HID);
    transpose_bf16<<<(HID * CH + 255) / 256, 256>>>(w2, p_w2T, HID, CH);

    // LN1
    ln_kernel<<<ROWS, 256>>>(x, ln1_g, ln1_b, p_h1);

    // QKV projection: [8192,768] x [2304,768]^T
    {
        EpiQKV e{p_q, p_k, p_vT};
        gemm_nt<128, 128, EpiQKV><<<dim3(ROWS / 128, (3 * CH) / 128, 1), 256>>>(
            p_h1, p_wqkvT, CH, 0, 0, e);
    }
    // scores: per (b,h): [1024,64] x [1024,64]^T  -> S
    {
        EpiScores e{p_S, temp, lw};
        gemm_nt<128, 128, EpiScores><<<dim3(SEQ / 128, SEQ / 128, BH), 256>>>(
            p_q, p_k, HD, (long long)SEQ * HD, (long long)SEQ * HD, e);
    }
    // softmax rows
    softmax_kernel<<<BH * SEQ, 256>>>(p_S, p_P);

    // O = P @ V : per (b,h): [1024,1024] x [64,1024]^T
    {
        EpiAV e{p_attn};
        gemm_nt<128, 64, EpiAV><<<dim3(SEQ / 128, 1, BH), 256>>>(
            p_P, p_vT, SEQ, (long long)SEQ * SEQ, (long long)HD * SEQ, e);
    }
    // proj + residual*ls1 -> x1 (fp32)
    {
        EpiResid e{x, b_proj, ls1, p_x1};
        gemm_nt<128, 128, EpiResid><<<dim3(ROWS / 128, CH / 128, 1), 256>>>(
            p_attn, p_wprojT, CH, 0, 0, e);
    }
    // LN2
    ln_kernel<<<ROWS, 256>>>(p_x1, ln2_g, ln2_b, p_h2);

    // MLP1 + gelu
    {
        EpiGelu e{b1, p_mid};
        gemm_nt<128, 128, EpiGelu><<<dim3(ROWS / 128, HID / 128, 1), 256>>>(
            p_h2, p_w1T, CH, 0, 0, e);
    }
    // MLP2 + residual*ls2 -> out (fp32)
    {
        EpiResid e{p_x1, b2, ls2, out};
        gemm_nt<128, 128, EpiResid><<<dim3(ROWS / 128, CH / 128, 1), 256>>>(
            p_mid, p_w2T, HID, 0, 0, e);
    }
}

// round 2
// speedup vs baseline: 1.3430x; 1.3430x over previous
#include <cuda_runtime.h>
#include <cuda_bf16.h>
#include <cstdint>
#include <math.h>

#define DI __device__ __forceinline__

static constexpr int B_DIM = 8;
static constexpr int SEQ   = 1024;
static constexpr int CH    = 768;
static constexpr int NH    = 12;
static constexpr int HD    = 64;
static constexpr int HID   = 3072;
static constexpr int ROWS  = B_DIM * SEQ;   // 8192
static constexpr int BH    = B_DIM * NH;    // 96

// ---------------- scratch: device globals (no runtime allocation) ------------
__device__ __nv_bfloat16 g_h1[ROWS * CH];
__device__ __nv_bfloat16 g_h2[ROWS * CH];
__device__ __nv_bfloat16 g_wqkvT[3 * CH * CH];
__device__ __nv_bfloat16 g_wprojT[CH * CH];
__device__ __nv_bfloat16 g_w1T[HID * CH];
__device__ __nv_bfloat16 g_w2T[CH * HID];
__device__ __nv_bfloat16 g_q[BH * SEQ * HD];
__device__ __nv_bfloat16 g_k[BH * SEQ * HD];
__device__ __nv_bfloat16 g_vT[BH * HD * SEQ];
__device__ __nv_bfloat16 g_S[(size_t)BH * SEQ * SEQ];
__device__ __nv_bfloat16 g_P[(size_t)BH * SEQ * SEQ];
__device__ __nv_bfloat16 g_attn[ROWS * CH];
__device__ float         g_x1[ROWS * CH];
__device__ __nv_bfloat16 g_mid[(size_t)ROWS * HID];

// ---------------- PTX helpers -------------------------------------------------

DI void cp16(uint32_t s, const void* g) {
    asm volatile("cp.async.cg.shared.global [%0], [%1], 16;\n" :: "r"(s), "l"(g));
}
DI void cp_commit() { asm volatile("cp.async.commit_group;\n"); }
template <int N> DI void cp_wait() { asm volatile("cp.async.wait_group %0;\n" :: "n"(N)); }

DI void ldsm_x4(uint32_t* r, uint32_t addr) {
    asm volatile("ldmatrix.sync.aligned.m8n8.x4.shared.b16 {%0,%1,%2,%3}, [%4];\n"
                 : "=r"(r[0]), "=r"(r[1]), "=r"(r[2]), "=r"(r[3]) : "r"(addr));
}

DI void mma_bf16(float* c, const uint32_t* a, uint32_t b0, uint32_t b1) {
    asm volatile(
        "mma.sync.aligned.m16n8k16.row.col.f32.bf16.bf16.f32 "
        "{%0,%1,%2,%3}, {%4,%5,%6,%7}, {%8,%9}, {%0,%1,%2,%3};\n"
        : "+f"(c[0]), "+f"(c[1]), "+f"(c[2]), "+f"(c[3])
        : "r"(a[0]), "r"(a[1]), "r"(a[2]), "r"(a[3]), "r"(b0), "r"(b1));
}

// ---------------- small helper kernels ---------------------------------------

// out[n][k] = bf16(in[k][n])  — tiled, coalesced both sides
__global__ void transpose_bf16(const float* __restrict__ in,
                               __nv_bfloat16* __restrict__ out, int K, int Nc) {
    __shared__ float tile[32][33];
    int kb = blockIdx.y * 32, nb = blockIdx.x * 32;
    int tx = threadIdx.x, ty = threadIdx.y;   // block (32, 8)
#pragma unroll
    for (int i = 0; i < 4; i++)
        tile[ty + i * 8][tx] = in[(size_t)(kb + ty + i * 8) * Nc + nb + tx];
    __syncthreads();
#pragma unroll
    for (int i = 0; i < 4; i++)
        out[(size_t)(nb + ty + i * 8) * K + kb + tx] =
            __float2bfloat16(tile[tx][ty + i * 8]);
}

// LayerNorm over CH=768, one block (256 thr) per row, fp32 in -> bf16 out
__global__ void ln_kernel(const float* __restrict__ x, const float* __restrict__ g,
                          const float* __restrict__ b, __nv_bfloat16* __restrict__ out) {
    int row = blockIdx.x;
    const float* xr = x + (size_t)row * CH;
    int t = threadIdx.x;
    float v0 = xr[t], v1 = xr[t + 256], v2 = xr[t + 512];
    float s  = v0 + v1 + v2;
    float s2 = v0 * v0 + v1 * v1 + v2 * v2;
#pragma unroll
    for (int o = 16; o; o >>= 1) {
        s  += __shfl_xor_sync(0xffffffffu, s,  o);
        s2 += __shfl_xor_sync(0xffffffffu, s2, o);
    }
    __shared__ float sh[16];
    int w = t >> 5, l = t & 31;
    if (l == 0) { sh[w] = s; sh[w + 8] = s2; }
    __syncthreads();
    float ts = 0.f, ts2 = 0.f;
#pragma unroll
    for (int i = 0; i < 8; i++) { ts += sh[i]; ts2 += sh[i + 8]; }
    float mu  = ts * (1.f / CH);
    float var = ts2 * (1.f / CH) - mu * mu;
    float inv = rsqrtf(var + 1e-5f);
    __nv_bfloat16* orow = out + (size_t)row * CH;
    orow[t]       = __float2bfloat16((v0 - mu) * inv * g[t]       + b[t]);
    orow[t + 256] = __float2bfloat16((v1 - mu) * inv * g[t + 256] + b[t + 256]);
    orow[t + 512] = __float2bfloat16((v2 - mu) * inv * g[t + 512] + b[t + 512]);
}

// Row softmax over SEQ=1024, one block (256 thr) per row. bf16 -> bf16
__global__ void softmax_kernel(const __nv_bfloat16* __restrict__ S,
                               __nv_bfloat16* __restrict__ P) {
    size_t row = blockIdx.x;
    const __nv_bfloat16* sr = S + row * SEQ;
    __nv_bfloat16* pr = P + row * SEQ;
    int t = threadIdx.x;
    const __nv_bfloat162* sp = reinterpret_cast<const __nv_bfloat162*>(sr) + t * 2;
    __nv_bfloat162 p0 = sp[0], p1 = sp[1];
    float v[4];
    v[0] = __bfloat162float(p0.x); v[1] = __bfloat162float(p0.y);
    v[2] = __bfloat162float(p1.x); v[3] = __bfloat162float(p1.y);

    float m = fmaxf(fmaxf(v[0], v[1]), fmaxf(v[2], v[3]));
#pragma unroll
    for (int o = 16; o; o >>= 1) m = fmaxf(m, __shfl_xor_sync(0xffffffffu, m, o));
    __shared__ float sh[8];
    int w = t >> 5, l = t & 31;
    if (l == 0) sh[w] = m;
    __syncthreads();
    float bm = sh[0];
#pragma unroll
    for (int i = 1; i < 8; i++) bm = fmaxf(bm, sh[i]);

    float e[4], sum = 0.f;
#pragma unroll
    for (int j = 0; j < 4; j++) { e[j] = __expf(v[j] - bm); sum += e[j]; }
#pragma unroll
    for (int o = 16; o; o >>= 1) sum += __shfl_xor_sync(0xffffffffu, sum, o);
    __syncthreads();
    if (l == 0) sh[w] = sum;
    __syncthreads();
    float bs = 0.f;
#pragma unroll
    for (int i = 0; i < 8; i++) bs += sh[i];
    float r = 1.f / bs;

    __nv_bfloat162* pp = reinterpret_cast<__nv_bfloat162*>(pr) + t * 2;
    pp[0] = __nv_bfloat162(__float2bfloat16(e[0] * r), __float2bfloat16(e[1] * r));
    pp[1] = __nv_bfloat162(__float2bfloat16(e[2] * r), __float2bfloat16(e[3] * r));
}

// ---------------- bf16 GEMM: cp.async 3-stage + ldmatrix ----------------------
// NT: C[M,Nn] = A[M,K] * B[Nn,K]^T.  BM x BN x 32 tiles, 256 threads.
// smem rows are 64B (32 bf16); 16B chunk c stored at c ^ ((row>>1)&3)  -> both
// cp.async stores and ldmatrix loads are bank-conflict-free.

template <int BM, int BN, class Epi>
__global__ void __launch_bounds__(256)
gemm_nt(const __nv_bfloat16* __restrict__ A, const __nv_bfloat16* __restrict__ Bm,
        int K, long long strideA, long long strideB, Epi epi) {
    constexpr int BK = 32;
    constexpr int STAGES = 3;
    constexpr int WN = BN / 2;                // 64 or 32
    constexpr int MT = 2;                     // warp M tile = 32
    constexpr int NT = WN / 8;                // 8 or 4
    constexpr int NH2 = NT / 2;               // n16 groups per warp
    constexpr int ASTG = BM * 64;             // bytes per A stage
    constexpr int BSTG = BN * 64;

    __shared__ __align__(16) uint8_t smem[STAGES * (ASTG + BSTG)];
    uint32_t sA0 = (uint32_t)__cvta_generic_to_shared(smem);
    uint32_t sB0 = sA0 + STAGES * ASTG;

    int bat = blockIdx.z;
    const __nv_bfloat16* Ab = A  + (size_t)bat * strideA;
    const __nv_bfloat16* Bb = Bm + (size_t)bat * strideB;
    int rowBase = blockIdx.x * BM, colBase = blockIdx.y * BN;
    int tid = threadIdx.x, lane = tid & 31, warp = tid >> 5;
    int wm = warp >> 1, wn = warp & 1;

    float acc[MT][NT][4];
#pragma unroll
    for (int i = 0; i < MT; i++)
#pragma unroll
        for (int j = 0; j < NT; j++)
#pragma unroll
            for (int q = 0; q < 4; q++) acc[i][j][q] = 0.f;

    const int KT = K / BK;

    auto issue = [&](int kt, int stage) {
#pragma unroll
        for (int i = 0; i < BM / 64; i++) {
            int idx = tid + i * 256;
            int r = idx >> 2, c = idx & 3;
            uint32_t d = sA0 + stage * ASTG + r * 64 + ((c ^ ((r >> 1) & 3)) << 4);
            cp16(d, Ab + (size_t)(rowBase + r) * K + kt * BK + c * 8);
        }
#pragma unroll
        for (int i = 0; i < BN / 64; i++) {
            int idx = tid + i * 256;
            int r = idx >> 2, c = idx & 3;
            uint32_t d = sB0 + stage * BSTG + r * 64 + ((c ^ ((r >> 1) & 3)) << 4);
            cp16(d, Bb + (size_t)(colBase + r) * K + kt * BK + c * 8);
        }
    };

    // prologue: stages 0,1
#pragma unroll
    for (int s = 0; s < STAGES - 1; s++) {
        if (s < KT) issue(s, s);
        cp_commit();
    }

    for (int kt = 0; kt < KT; kt++) {
        cp_wait<STAGES - 2>();
        __syncthreads();
        int nk = kt + STAGES - 1;
        if (nk < KT) issue(nk, nk % STAGES);
        cp_commit();

        int stage = kt % STAGES;
        uint32_t aB = sA0 + stage * ASTG;
        uint32_t bB = sB0 + stage * BSTG;
#pragma unroll
        for (int kk = 0; kk < 2; kk++) {
            uint32_t afr[MT][4], bfr[NH2][4];
            int c = kk * 2 + (lane >> 4);
#pragma unroll
            for (int mt = 0; mt < MT; mt++) {
                int r = wm * 32 + mt * 16 + (lane & 15);
                ldsm_x4(afr[mt], aB + r * 64 + ((c ^ ((r >> 1) & 3)) << 4));
            }
#pragma unroll
            for (int j = 0; j < NH2; j++) {
                int r = wn * WN + j * 16 + (lane & 15);
                ldsm_x4(bfr[j], bB + r * 64 + ((c ^ ((r >> 1) & 3)) << 4));
            }
#pragma unroll
            for (int mt = 0; mt < MT; mt++)
#pragma unroll
                for (int j = 0; j < NH2; j++) {
                    mma_bf16(acc[mt][2 * j],     afr[mt], bfr[j][0], bfr[j][2]);
                    mma_bf16(acc[mt][2 * j + 1], afr[mt], bfr[j][1], bfr[j][3]);
                }
        }
        __syncthreads();
    }

    int g = lane >> 2, ct = lane & 3;
#pragma unroll
    for (int mt = 0; mt < MT; mt++)
#pragma unroll
        for (int nt = 0; nt < NT; nt++) {
            int r = rowBase + wm * 32 + mt * 16 + g;
            int c = colBase + wn * WN + nt * 8 + ct * 2;
            epi(r,     c,     bat, acc[mt][nt][0]);
            epi(r,     c + 1, bat, acc[mt][nt][1]);
            epi(r + 8, c,     bat, acc[mt][nt][2]);
            epi(r + 8, c + 1, bat, acc[mt][nt][3]);
        }
}

// ---------------- epilogues ---------------------------------------------------

struct EpiQKV {
    __nv_bfloat16 *q, *k, *vT;
    DI void operator()(int r, int c, int, float v) const {
        int s = c / CH;
        int rem = c - s * CH;
        int h = rem >> 6, d = rem & 63;
        int b = r >> 10, n = r & 1023;
        int bh = b * NH + h;
        __nv_bfloat16 bv = __float2bfloat16(v);
        if (s == 0)      q [((size_t)bh * SEQ + n) * HD + d] = bv;
        else if (s == 1) k [((size_t)bh * SEQ + n) * HD + d] = bv;
        else             vT[((size_t)bh * HD  + d) * SEQ + n] = bv;
    }
};

struct EpiScores {
    __nv_bfloat16* S;
    const float* temp;
    const float* lw;
    DI void operator()(int n, int m, int bh, float v) const {
        int h = bh % NH;
        float scale = __expf(__ldg(temp + h));
        float yi = (float)(n >> 5) * (1.f / 31.f), xi = (float)(n & 31) * (1.f / 31.f);
        float yj = (float)(m >> 5) * (1.f / 31.f), xj = (float)(m & 31) * (1.f / 31.f);
        float dy = yi - yj, dx = xi - xj;
        float loc = -0.5f * (dy * dy + dx * dx);
        S[((size_t)bh * SEQ + n) * SEQ + m] =
            __float2bfloat16(v * scale + __ldg(lw + h) * loc);
    }
};

struct EpiAV {
    __nv_bfloat16* attn;
    DI void operator()(int n, int d, int bh, float v) const {
        int b = bh / NH, h = bh % NH;
        attn[((size_t)(b * SEQ + n)) * CH + h * HD + d] = __float2bfloat16(v);
    }
};

struct EpiResid {
    const float* base;
    const float* bias;
    const float* ls;
    float* out;
    DI void operator()(int r, int c, int, float v) const {
        size_t i = (size_t)r * CH + c;
        out[i] = base[i] + (v + __ldg(bias + c)) * __ldg(ls + c);
    }
};

struct EpiGelu {
    const float* bias;
    __nv_bfloat16* out;
    DI void operator()(int r, int c, int, float v) const {
        float t = v + __ldg(bias + c);
        float gl = 0.5f * t * (1.f + erff(t * 0.70710678118654752f));
        out[(size_t)r * HID + c] = __float2bfloat16(gl);
    }
};

// ---------------- launch ------------------------------------------------------

extern "C" void kernel_launch(void* const* d_in, const int* in_sizes, int n_in,
                              void* d_out, int out_size) {
    (void)in_sizes; (void)n_in; (void)out_size;
    const float* x      = (const float*)d_in[0];
    const float* w_qkv  = (const float*)d_in[1];
    const float* w_proj = (const float*)d_in[2];
    const float* b_proj = (const float*)d_in[3];
    const float* ln1_g  = (const float*)d_in[4];
    const float* ln1_b  = (const float*)d_in[5];
    const float* ln2_g  = (const float*)d_in[6];
    const float* ln2_b  = (const float*)d_in[7];
    const float* temp   = (const float*)d_in[8];
    const float* lw     = (const float*)d_in[9];
    const float* ls1    = (const float*)d_in[10];
    const float* ls2    = (const float*)d_in[11];
    const float* w1     = (const float*)d_in[12];
    const float* b1     = (const float*)d_in[13];
    const float* w2     = (const float*)d_in[14];
    const float* b2     = (const float*)d_in[15];
    float* out = (float*)d_out;

    __nv_bfloat16 *p_h1, *p_h2, *p_wqkvT, *p_wprojT, *p_w1T, *p_w2T;
    __nv_bfloat16 *p_q, *p_k, *p_vT, *p_S, *p_P, *p_attn, *p_mid;
    float* p_x1;
    cudaGetSymbolAddress((void**)&p_h1, g_h1);
    cudaGetSymbolAddress((void**)&p_h2, g_h2);
    cudaGetSymbolAddress((void**)&p_wqkvT, g_wqkvT);
    cudaGetSymbolAddress((void**)&p_wprojT, g_wprojT);
    cudaGetSymbolAddress((void**)&p_w1T, g_w1T);
    cudaGetSymbolAddress((void**)&p_w2T, g_w2T);
    cudaGetSymbolAddress((void**)&p_q, g_q);
    cudaGetSymbolAddress((void**)&p_k, g_k);
    cudaGetSymbolAddress((void**)&p_vT, g_vT);
    cudaGetSymbolAddress((void**)&p_S, g_S);
    cudaGetSymbolAddress((void**)&p_P, g_P);
    cudaGetSymbolAddress((void**)&p_attn, g_attn);
    cudaGetSymbolAddress((void**)&p_x1, g_x1);
    cudaGetSymbolAddress((void**)&p_mid, g_mid);

    dim3 tb(32, 8);
    transpose_bf16<<<dim3((3 * CH) / 32, CH / 32), tb>>>(w_qkv, p_wqkvT, CH, 3 * CH);
    transpose_bf16<<<dim3(CH / 32, CH / 32), tb>>>(w_proj, p_wprojT, CH, CH);
    transpose_bf16<<<dim3(HID / 32, CH / 32), tb>>>(w1, p_w1T, CH, HID);
    transpose_bf16<<<dim3(CH / 32, HID / 32), tb>>>(w2, p_w2T, HID, CH);

    ln_kernel<<<ROWS, 256>>>(x, ln1_g, ln1_b, p_h1);

    {   // QKV: [8192,768] x [2304,768]^T
        EpiQKV e{p_q, p_k, p_vT};
        gemm_nt<128, 128, EpiQKV><<<dim3(ROWS / 128, (3 * CH) / 128, 1), 256>>>(
            p_h1, p_wqkvT, CH, 0, 0, e);
    }
    {   // scores: per (b,h) [1024,64] x [1024,64]^T
        EpiScores e{p_S, temp, lw};
        gemm_nt<128, 128, EpiScores><<<dim3(SEQ / 128, SEQ / 128, BH), 256>>>(
            p_q, p_k, HD, (long long)SEQ * HD, (long long)SEQ * HD, e);
    }
    softmax_kernel<<<BH * SEQ, 256>>>(p_S, p_P);

    {   // O = P @ V : per (b,h) [1024,1024] x [64,1024]^T
        EpiAV e{p_attn};
        gemm_nt<128, 64, EpiAV><<<dim3(SEQ / 128, 1, BH), 256>>>(
            p_P, p_vT, SEQ, (long long)SEQ * SEQ, (long long)HD * SEQ, e);
    }
    {   // proj + residual*ls1 -> x1 (fp32)
        EpiResid e{x, b_proj, ls1, p_x1};
        gemm_nt<128, 128, EpiResid><<<dim3(ROWS / 128, CH / 128, 1), 256>>>(
            p_attn, p_wprojT, CH, 0, 0, e);
    }
    ln_kernel<<<ROWS, 256>>>(p_x1, ln2_g, ln2_b, p_h2);

    {   // MLP1 + gelu
        EpiGelu e{b1, p_mid};
        gemm_nt<128, 128, EpiGelu><<<dim3(ROWS / 128, HID / 128, 1), 256>>>(
            p_h2, p_w1T, CH, 0, 0, e);
    }
    {   // MLP2 + residual*ls2 -> out (fp32)
        EpiResid e{p_x1, b2, ls2, out};
        gemm_nt<128, 128, EpiResid><<<dim3(ROWS / 128, CH / 128, 1), 256>>>(
            p_mid, p_w2T, HID, 0, 0, e);
    }
}

// round 4
// speedup vs baseline: 1.8765x; 1.3972x over previous
#include <cuda_runtime.h>
#include <cuda_bf16.h>
#include <cstdint>
#include <math.h>

#define DI __device__ __forceinline__

static constexpr int B_DIM = 8;
static constexpr int SEQ   = 1024;
static constexpr int CH    = 768;
static constexpr int NH    = 12;
static constexpr int HD    = 64;
static constexpr int HID   = 3072;
static constexpr int ROWS  = B_DIM * SEQ;   // 8192
static constexpr int BH    = B_DIM * NH;    // 96

// ---------------- scratch: device globals (no runtime allocation) ------------
__device__ __nv_bfloat16 g_h1[ROWS * CH];
__device__ __nv_bfloat16 g_h2[ROWS * CH];
__device__ __nv_bfloat16 g_wqkvT[3 * CH * CH];
__device__ __nv_bfloat16 g_wprojT[CH * CH];
__device__ __nv_bfloat16 g_w1T[HID * CH];
__device__ __nv_bfloat16 g_w2T[CH * HID];
__device__ __nv_bfloat16 g_q[BH * SEQ * HD];
__device__ __nv_bfloat16 g_k[BH * SEQ * HD];
__device__ __nv_bfloat16 g_v[BH * SEQ * HD];
__device__ __nv_bfloat16 g_attn[ROWS * CH];
__device__ float         g_x1[ROWS * CH];
__device__ __nv_bfloat16 g_mid[(size_t)ROWS * HID];

// ---------------- PTX helpers -------------------------------------------------

DI void cp16(uint32_t s, const void* g) {
    asm volatile("cp.async.cg.shared.global [%0], [%1], 16;\n" :: "r"(s), "l"(g));
}
DI void cp_commit() { asm volatile("cp.async.commit_group;\n"); }
template <int N> DI void cp_wait() { asm volatile("cp.async.wait_group %0;\n" :: "n"(N)); }

DI void ldsm_x4(uint32_t* r, uint32_t addr) {
    asm volatile("ldmatrix.sync.aligned.m8n8.x4.shared.b16 {%0,%1,%2,%3}, [%4];\n"
                 : "=r"(r[0]), "=r"(r[1]), "=r"(r[2]), "=r"(r[3]) : "r"(addr));
}
DI void ldsm_x4_t(uint32_t* r, uint32_t addr) {
    asm volatile("ldmatrix.sync.aligned.m8n8.x4.trans.shared.b16 {%0,%1,%2,%3}, [%4];\n"
                 : "=r"(r[0]), "=r"(r[1]), "=r"(r[2]), "=r"(r[3]) : "r"(addr));
}

DI void mma_bf16(float* c, const uint32_t* a, uint32_t b0, uint32_t b1) {
    asm volatile(
        "mma.sync.aligned.m16n8k16.row.col.f32.bf16.bf16.f32 "
        "{%0,%1,%2,%3}, {%4,%5,%6,%7}, {%8,%9}, {%0,%1,%2,%3};\n"
        : "+f"(c[0]), "+f"(c[1]), "+f"(c[2]), "+f"(c[3])
        : "r"(a[0]), "r"(a[1]), "r"(a[2]), "r"(a[3]), "r"(b0), "r"(b1));
}

DI uint32_t packbf(float lo, float hi) {
    __nv_bfloat162 t = __float22bfloat162_rn(make_float2(lo, hi));
    return *reinterpret_cast<uint32_t*>(&t);
}

// ---------------- small helper kernels ---------------------------------------

__global__ void transpose_bf16(const float* __restrict__ in,
                               __nv_bfloat16* __restrict__ out, int K, int Nc) {
    __shared__ float tile[32][33];
    int kb = blockIdx.y * 32, nb = blockIdx.x * 32;
    int tx = threadIdx.x, ty = threadIdx.y;   // block (32, 8)
#pragma unroll
    for (int i = 0; i < 4; i++)
        tile[ty + i * 8][tx] = in[(size_t)(kb + ty + i * 8) * Nc + nb + tx];
    __syncthreads();
#pragma unroll
    for (int i = 0; i < 4; i++)
        out[(size_t)(nb + ty + i * 8) * K + kb + tx] =
            __float2bfloat16(tile[tx][ty + i * 8]);
}

__global__ void ln_kernel(const float* __restrict__ x, const float* __restrict__ g,
                          const float* __restrict__ b, __nv_bfloat16* __restrict__ out) {
    int row = blockIdx.x;
    const float* xr = x + (size_t)row * CH;
    int t = threadIdx.x;
    float v0 = xr[t], v1 = xr[t + 256], v2 = xr[t + 512];
    float s  = v0 + v1 + v2;
    float s2 = v0 * v0 + v1 * v1 + v2 * v2;
#pragma unroll
    for (int o = 16; o; o >>= 1) {
        s  += __shfl_xor_sync(0xffffffffu, s,  o);
        s2 += __shfl_xor_sync(0xffffffffu, s2, o);
    }
    __shared__ float sh[16];
    int w = t >> 5, l = t & 31;
    if (l == 0) { sh[w] = s; sh[w + 8] = s2; }
    __syncthreads();
    float ts = 0.f, ts2 = 0.f;
#pragma unroll
    for (int i = 0; i < 8; i++) { ts += sh[i]; ts2 += sh[i + 8]; }
    float mu  = ts * (1.f / CH);
    float var = ts2 * (1.f / CH) - mu * mu;
    float inv = rsqrtf(var + 1e-5f);
    __nv_bfloat16* orow = out + (size_t)row * CH;
    orow[t]       = __float2bfloat16((v0 - mu) * inv * g[t]       + b[t]);
    orow[t + 256] = __float2bfloat16((v1 - mu) * inv * g[t + 256] + b[t + 256]);
    orow[t + 512] = __float2bfloat16((v2 - mu) * inv * g[t + 512] + b[t + 512]);
}

// ---------------- fused flash attention ---------------------------------------
// grid (8 q-tiles, 96 bh), 256 threads (8 warps, 16 q-rows each).
// Q tile 128x64 resident; K/V tiles 64x64 double-buffered via cp.async.
// loc(n,m) = yn*ym + xn*xm + cn + cm  with c = -0.5*(y^2+x^2), coords i/31.

__global__ void __launch_bounds__(256)
flash_attn(const __nv_bfloat16* __restrict__ Q, const __nv_bfloat16* __restrict__ K,
           const __nv_bfloat16* __restrict__ V, const float* __restrict__ temp,
           const float* __restrict__ lw, __nv_bfloat16* __restrict__ attn) {
    constexpr int ITERS = SEQ / 64;           // 16
    __shared__ __align__(16) uint8_t smem[49152];
    uint32_t sQ = (uint32_t)__cvta_generic_to_shared(smem);
    uint32_t sK = sQ + 16384;                 // 2 stages x 8192
    uint32_t sV = sK + 16384;                 // 2 stages x 8192

    int bh = blockIdx.y;
    int b = bh / NH, h = bh % NH;
    int qbase = blockIdx.x * 128;
    const __nv_bfloat16* qb = Q + ((size_t)bh * SEQ + qbase) * HD;
    const __nv_bfloat16* kb = K + (size_t)bh * SEQ * HD;
    const __nv_bfloat16* vb = V + (size_t)bh * SEQ * HD;

    int tid = threadIdx.x, lane = tid & 31, w = tid >> 5;
    int g = lane >> 2, ct = lane & 3;

    auto issue_kv = [&](int t, int stage) {
#pragma unroll
        for (int i = 0; i < 2; i++) {
            int idx = tid + i * 256;
            int r = idx >> 3, c = idx & 7;
            uint32_t sw = (uint32_t)((c ^ (r & 7)) << 4);
            cp16(sK + stage * 8192 + r * 128 + sw, kb + (size_t)(t * 64 + r) * HD + c * 8);
            cp16(sV + stage * 8192 + r * 128 + sw, vb + (size_t)(t * 64 + r) * HD + c * 8);
        }
    };

    // prologue: Q + KV(0) as group0, KV(1) as group1
#pragma unroll
    for (int i = 0; i < 4; i++) {
        int idx = tid + i * 256;
        int r = idx >> 3, c = idx & 7;
        cp16(sQ + r * 128 + ((c ^ (r & 7)) << 4), qb + (size_t)r * HD + c * 8);
    }
    issue_kv(0, 0);
    cp_commit();
    issue_kv(1, 1);
    cp_commit();

    const float scale = __expf(__ldg(temp + h));
    const float lwh   = __ldg(lw + h);
    const float inv31 = 1.f / 31.f;
    int r0i = qbase + w * 16 + g, r1i = r0i + 8;
    float y0 = (float)(r0i >> 5) * inv31, x0 = (float)(r0i & 31) * inv31;
    float y1 = (float)(r1i >> 5) * inv31, x1 = (float)(r1i & 31) * inv31;
    float c0r = -0.5f * (y0 * y0 + x0 * x0);
    float c1r = -0.5f * (y1 * y1 + x1 * x1);

    float oacc[8][4];
#pragma unroll
    for (int j = 0; j < 8; j++)
#pragma unroll
        for (int q = 0; q < 4; q++) oacc[j][q] = 0.f;
    float mrun0 = -1e30f, mrun1 = -1e30f, l0 = 0.f, l1 = 0.f;

    uint32_t aq[4][4];

    for (int t = 0; t < ITERS; t++) {
        cp_wait<1>();
        __syncthreads();
        if (t == 0) {   // Q fragments, loaded once
#pragma unroll
            for (int ks = 0; ks < 4; ks++) {
                int c = ks * 2 + (lane >> 4);
                int r = w * 16 + (lane & 15);
                ldsm_x4(aq[ks], sQ + r * 128 + ((c ^ (r & 7)) << 4));
            }
        }
        int stage = t & 1;
        uint32_t kBase = sK + stage * 8192;
        uint32_t vBase = sV + stage * 8192;

        // ---- S = Q K^T ----
        float sacc[8][4];
#pragma unroll
        for (int j = 0; j < 8; j++)
#pragma unroll
            for (int q = 0; q < 4; q++) sacc[j][q] = 0.f;
#pragma unroll
        for (int ks = 0; ks < 4; ks++) {
            int c = ks * 2 + (lane >> 4);
            uint32_t bk[4][4];
#pragma unroll
            for (int j = 0; j < 4; j++) {
                int r = j * 16 + (lane & 15);
                ldsm_x4(bk[j], kBase + r * 128 + ((c ^ (r & 7)) << 4));
            }
#pragma unroll
            for (int j = 0; j < 4; j++) {
                mma_bf16(sacc[2 * j],     aq[ks], bk[j][0], bk[j][2]);
                mma_bf16(sacc[2 * j + 1], aq[ks], bk[j][1], bk[j][3]);
            }
        }

        // ---- bias + online softmax ----
        int colbase = t * 64;
        float mx0 = -1e30f, mx1 = -1e30f;
#pragma unroll
        for (int nt = 0; nt < 8; nt++) {
#pragma unroll
            for (int e = 0; e < 2; e++) {
                int m = colbase + nt * 8 + ct * 2 + e;
                float ym = (float)(m >> 5) * inv31, xm = (float)(m & 31) * inv31;
                float cm = -0.5f * (ym * ym + xm * xm);
                float s0 = sacc[nt][e]     * scale + lwh * (y0 * ym + x0 * xm + c0r + cm);
                float s1 = sacc[nt][2 + e] * scale + lwh * (y1 * ym + x1 * xm + c1r + cm);
                sacc[nt][e] = s0; sacc[nt][2 + e] = s1;
                mx0 = fmaxf(mx0, s0); mx1 = fmaxf(mx1, s1);
            }
        }
        mx0 = fmaxf(mx0, __shfl_xor_sync(0xffffffffu, mx0, 1));
        mx0 = fmaxf(mx0, __shfl_xor_sync(0xffffffffu, mx0, 2));
        mx1 = fmaxf(mx1, __shfl_xor_sync(0xffffffffu, mx1, 1));
        mx1 = fmaxf(mx1, __shfl_xor_sync(0xffffffffu, mx1, 2));
        float mn0 = fmaxf(mrun0, mx0), mn1 = fmaxf(mrun1, mx1);
        float al0 = __expf(mrun0 - mn0), al1 = __expf(mrun1 - mn1);
        mrun0 = mn0; mrun1 = mn1;
        l0 *= al0; l1 *= al1;
#pragma unroll
        for (int j = 0; j < 8; j++) {
            oacc[j][0] *= al0; oacc[j][1] *= al0;
            oacc[j][2] *= al1; oacc[j][3] *= al1;
        }
#pragma unroll
        for (int nt = 0; nt < 8; nt++) {
            float p0 = __expf(sacc[nt][0] - mn0);
            float p1 = __expf(sacc[nt][1] - mn0);
            float p2 = __expf(sacc[nt][2] - mn1);
            float p3 = __expf(sacc[nt][3] - mn1);
            l0 += p0 + p1; l1 += p2 + p3;
            sacc[nt][0] = p0; sacc[nt][1] = p1; sacc[nt][2] = p2; sacc[nt][3] = p3;
        }
        // P -> A fragments
        uint32_t ap[4][4];
#pragma unroll
        for (int ks = 0; ks < 4; ks++) {
            ap[ks][0] = packbf(sacc[2 * ks][0],     sacc[2 * ks][1]);
            ap[ks][1] = packbf(sacc[2 * ks][2],     sacc[2 * ks][3]);
            ap[ks][2] = packbf(sacc[2 * ks + 1][0], sacc[2 * ks + 1][1]);
            ap[ks][3] = packbf(sacc[2 * ks + 1][2], sacc[2 * ks + 1][3]);
        }

        // ---- O += P V ----
#pragma unroll
        for (int ks = 0; ks < 4; ks++) {
            int rr = ks * 16 + (lane & 15);
#pragma unroll
            for (int j = 0; j < 4; j++) {
                int c = 2 * j + (lane >> 4);
                uint32_t vf[4];
                ldsm_x4_t(vf, vBase + rr * 128 + ((c ^ (rr & 7)) << 4));
                mma_bf16(oacc[2 * j],     ap[ks], vf[0], vf[1]);
                mma_bf16(oacc[2 * j + 1], ap[ks], vf[2], vf[3]);
            }
        }

        __syncthreads();          // done reading stage
        if (t + 2 < ITERS) issue_kv(t + 2, stage);
        cp_commit();
    }

    // ---- normalize + store ----
    l0 += __shfl_xor_sync(0xffffffffu, l0, 1);
    l0 += __shfl_xor_sync(0xffffffffu, l0, 2);
    l1 += __shfl_xor_sync(0xffffffffu, l1, 1);
    l1 += __shfl_xor_sync(0xffffffffu, l1, 2);
    float inv0 = 1.f / l0, inv1 = 1.f / l1;
    __nv_bfloat16* o0 = attn + ((size_t)(b * SEQ + r0i)) * CH + h * HD;
    __nv_bfloat16* o1 = attn + ((size_t)(b * SEQ + r1i)) * CH + h * HD;
#pragma unroll
    for (int j = 0; j < 8; j++) {
        int col = j * 8 + ct * 2;
        __nv_bfloat162 v0 = __float22bfloat162_rn(
            make_float2(oacc[j][0] * inv0, oacc[j][1] * inv0));
        __nv_bfloat162 v1 = __float22bfloat162_rn(
            make_float2(oacc[j][2] * inv1, oacc[j][3] * inv1));
        *reinterpret_cast<__nv_bfloat162*>(o0 + col) = v0;
        *reinterpret_cast<__nv_bfloat162*>(o1 + col) = v1;
    }
}

// ---------------- bf16 GEMM: cp.async 3-stage + ldmatrix ----------------------

template <int BM, int BN, class Epi>
__global__ void __launch_bounds__(256)
gemm_nt(const __nv_bfloat16* __restrict__ A, const __nv_bfloat16* __restrict__ Bm,
        int K, long long strideA, long long strideB, Epi epi) {
    constexpr int BK = 32;
    constexpr int STAGES = 3;
    constexpr int WN = BN / 2;
    constexpr int MT = 2;
    constexpr int NT = WN / 8;
    constexpr int NH2 = NT / 2;
    constexpr int ASTG = BM * 64;
    constexpr int BSTG = BN * 64;

    __shared__ __align__(16) uint8_t smem[STAGES * (ASTG + BSTG)];
    uint32_t sA0 = (uint32_t)__cvta_generic_to_shared(smem);
    uint32_t sB0 = sA0 + STAGES * ASTG;

    int bat = blockIdx.z;
    const __nv_bfloat16* Ab = A  + (size_t)bat * strideA;
    const __nv_bfloat16* Bb = Bm + (size_t)bat * strideB;
    int rowBase = blockIdx.x * BM, colBase = blockIdx.y * BN;
    int tid = threadIdx.x, lane = tid & 31, warp = tid >> 5;
    int wm = warp >> 1, wn = warp & 1;

    float acc[MT][NT][4];
#pragma unroll
    for (int i = 0; i < MT; i++)
#pragma unroll
        for (int j = 0; j < NT; j++)
#pragma unroll
            for (int q = 0; q < 4; q++) acc[i][j][q] = 0.f;

    const int KT = K / BK;

    auto issue = [&](int kt, int stage) {
#pragma unroll
        for (int i = 0; i < BM / 64; i++) {
            int idx = tid + i * 256;
            int r = idx >> 2, c = idx & 3;
            uint32_t d = sA0 + stage * ASTG + r * 64 + ((c ^ ((r >> 1) & 3)) << 4);
            cp16(d, Ab + (size_t)(rowBase + r) * K + kt * BK + c * 8);
        }
#pragma unroll
        for (int i = 0; i < BN / 64; i++) {
            int idx = tid + i * 256;
            int r = idx >> 2, c = idx & 3;
            uint32_t d = sB0 + stage * BSTG + r * 64 + ((c ^ ((r >> 1) & 3)) << 4);
            cp16(d, Bb + (size_t)(colBase + r) * K + kt * BK + c * 8);
        }
    };

#pragma unroll
    for (int s = 0; s < STAGES - 1; s++) {
        if (s < KT) issue(s, s);
        cp_commit();
    }

    for (int kt = 0; kt < KT; kt++) {
        cp_wait<STAGES - 2>();
        __syncthreads();
        int nk = kt + STAGES - 1;
        if (nk < KT) issue(nk, nk % STAGES);
        cp_commit();

        int stage = kt % STAGES;
        uint32_t aB = sA0 + stage * ASTG;
        uint32_t bB = sB0 + stage * BSTG;
#pragma unroll
        for (int kk = 0; kk < 2; kk++) {
            uint32_t afr[MT][4], bfr[NH2][4];
            int c = kk * 2 + (lane >> 4);
#pragma unroll
            for (int mt = 0; mt < MT; mt++) {
                int r = wm * 32 + mt * 16 + (lane & 15);
                ldsm_x4(afr[mt], aB + r * 64 + ((c ^ ((r >> 1) & 3)) << 4));
            }
#pragma unroll
            for (int j = 0; j < NH2; j++) {
                int r = wn * WN + j * 16 + (lane & 15);
                ldsm_x4(bfr[j], bB + r * 64 + ((c ^ ((r >> 1) & 3)) << 4));
            }
#pragma unroll
            for (int mt = 0; mt < MT; mt++)
#pragma unroll
                for (int j = 0; j < NH2; j++) {
                    mma_bf16(acc[mt][2 * j],     afr[mt], bfr[j][0], bfr[j][2]);
                    mma_bf16(acc[mt][2 * j + 1], afr[mt], bfr[j][1], bfr[j][3]);
                }
        }
        __syncthreads();
    }

    int g = lane >> 2, ct = lane & 3;
#pragma unroll
    for (int mt = 0; mt < MT; mt++)
#pragma unroll
        for (int nt = 0; nt < NT; nt++) {
            int r = rowBase + wm * 32 + mt * 16 + g;
            int c = colBase + wn * WN + nt * 8 + ct * 2;
            epi(r,     c,     bat, acc[mt][nt][0]);
            epi(r,     c + 1, bat, acc[mt][nt][1]);
            epi(r + 8, c,     bat, acc[mt][nt][2]);
            epi(r + 8, c + 1, bat, acc[mt][nt][3]);
        }
}

// ---------------- epilogues ---------------------------------------------------

struct EpiQKV {
    __nv_bfloat16 *q, *k, *v;
    DI void operator()(int r, int c, int, float val) const {
        int s = c / CH;
        int rem = c - s * CH;
        int h = rem >> 6, d = rem & 63;
        int b = r >> 10, n = r & 1023;
        int bh = b * NH + h;
        __nv_bfloat16 bv = __float2bfloat16(val);
        size_t idx = ((size_t)bh * SEQ + n) * HD + d;
        if (s == 0)      q[idx] = bv;
        else if (s == 1) k[idx] = bv;
        else             v[idx] = bv;
    }
};

struct EpiResid {
    const float* base;
    const float* bias;
    const float* ls;
    float* out;
    DI void operator()(int r, int c, int, float v) const {
        size_t i = (size_t)r * CH + c;
        out[i] = base[i] + (v + __ldg(bias + c)) * __ldg(ls + c);
    }
};

struct EpiGelu {
    const float* bias;
    __nv_bfloat16* out;
    DI void operator()(int r, int c, int, float v) const {
        float t = v + __ldg(bias + c);
        float gl = 0.5f * t * (1.f + erff(t * 0.70710678118654752f));
        out[(size_t)r * HID + c] = __float2bfloat16(gl);
    }
};

// ---------------- launch ------------------------------------------------------

extern "C" void kernel_launch(void* const* d_in, const int* in_sizes, int n_in,
                              void* d_out, int out_size) {
    (void)in_sizes; (void)n_in; (void)out_size;
    const float* x      = (const float*)d_in[0];
    const float* w_qkv  = (const float*)d_in[1];
    const float* w_proj = (const float*)d_in[2];
    const float* b_proj = (const float*)d_in[3];
    const float* ln1_g  = (const float*)d_in[4];
    const float* ln1_b  = (const float*)d_in[5];
    const float* ln2_g  = (const float*)d_in[6];
    const float* ln2_b  = (const float*)d_in[7];
    const float* temp   = (const float*)d_in[8];
    const float* lw     = (const float*)d_in[9];
    const float* ls1    = (const float*)d_in[10];
    const float* ls2    = (const float*)d_in[11];
    const float* w1     = (const float*)d_in[12];
    const float* b1     = (const float*)d_in[13];
    const float* w2     = (const float*)d_in[14];
    const float* b2     = (const float*)d_in[15];
    float* out = (float*)d_out;

    __nv_bfloat16 *p_h1, *p_h2, *p_wqkvT, *p_wprojT, *p_w1T, *p_w2T;
    __nv_bfloat16 *p_q, *p_k, *p_v, *p_attn, *p_mid;
    float* p_x1;
    cudaGetSymbolAddress((void**)&p_h1, g_h1);
    cudaGetSymbolAddress((void**)&p_h2, g_h2);
    cudaGetSymbolAddress((void**)&p_wqkvT, g_wqkvT);
    cudaGetSymbolAddress((void**)&p_wprojT, g_wprojT);
    cudaGetSymbolAddress((void**)&p_w1T, g_w1T);
    cudaGetSymbolAddress((void**)&p_w2T, g_w2T);
    cudaGetSymbolAddress((void**)&p_q, g_q);
    cudaGetSymbolAddress((void**)&p_k, g_k);
    cudaGetSymbolAddress((void**)&p_v, g_v);
    cudaGetSymbolAddress((void**)&p_attn, g_attn);
    cudaGetSymbolAddress((void**)&p_x1, g_x1);
    cudaGetSymbolAddress((void**)&p_mid, g_mid);

    dim3 tb(32, 8);
    transpose_bf16<<<dim3((3 * CH) / 32, CH / 32), tb>>>(w_qkv, p_wqkvT, CH, 3 * CH);
    transpose_bf16<<<dim3(CH / 32, CH / 32), tb>>>(w_proj, p_wprojT, CH, CH);
    transpose_bf16<<<dim3(HID / 32, CH / 32), tb>>>(w1, p_w1T, CH, HID);
    transpose_bf16<<<dim3(CH / 32, HID / 32), tb>>>(w2, p_w2T, HID, CH);

    ln_kernel<<<ROWS, 256>>>(x, ln1_g, ln1_b, p_h1);

    {   // QKV: [8192,768] x [2304,768]^T
        EpiQKV e{p_q, p_k, p_v};
        gemm_nt<128, 128, EpiQKV><<<dim3(ROWS / 128, (3 * CH) / 128, 1), 256>>>(
            p_h1, p_wqkvT, CH, 0, 0, e);
    }

    // fused attention: scores + bias + softmax + PV
    flash_attn<<<dim3(SEQ / 128, BH), 256>>>(p_q, p_k, p_v, temp, lw, p_attn);

    {   // proj + residual*ls1 -> x1 (fp32)
        EpiResid e{x, b_proj, ls1, p_x1};
        gemm_nt<128, 128, EpiResid><<<dim3(ROWS / 128, CH / 128, 1), 256>>>(
            p_attn, p_wprojT, CH, 0, 0, e);
    }
    ln_kernel<<<ROWS, 256>>>(p_x1, ln2_g, ln2_b, p_h2);

    {   // MLP1 + gelu
        EpiGelu e{b1, p_mid};
        gemm_nt<128, 128, EpiGelu><<<dim3(ROWS / 128, HID / 128, 1), 256>>>(
            p_h2, p_w1T, CH, 0, 0, e);
    }
    {   // MLP2 + residual*ls2 -> out (fp32)
        EpiResid e{p_x1, b2, ls2, out};
        gemm_nt<128, 128, EpiResid><<<dim3(ROWS / 128, CH / 128, 1), 256>>>(
            p_mid, p_w2T, HID, 0, 0, e);
    }
}

// round 6
// speedup vs baseline: 1.9872x; 1.0590x over previous
#include <cuda_runtime.h>
#include <cuda_bf16.h>
#include <cstdint>
#include <math.h>

#define DI __device__ __forceinline__

static constexpr int B_DIM = 8;
static constexpr int SEQ   = 1024;
static constexpr int CH    = 768;
static constexpr int NH    = 12;
static constexpr int HD    = 64;
static constexpr int HID   = 3072;
static constexpr int ROWS  = B_DIM * SEQ;   // 8192
static constexpr int BH    = B_DIM * NH;    // 96

// ---------------- scratch: device globals (no runtime allocation) ------------
__device__ __nv_bfloat16 g_h1[ROWS * CH];
__device__ __nv_bfloat16 g_h2[ROWS * CH];
__device__ __nv_bfloat16 g_wqkvT[3 * CH * CH];
__device__ __nv_bfloat16 g_wprojT[CH * CH];
__device__ __nv_bfloat16 g_w1T[HID * CH];
__device__ __nv_bfloat16 g_w2T[CH * HID];
__device__ __nv_bfloat16 g_q[BH * SEQ * HD];
__device__ __nv_bfloat16 g_k[BH * SEQ * HD];
__device__ __nv_bfloat16 g_v[BH * SEQ * HD];
__device__ __nv_bfloat16 g_attn[ROWS * CH];
__device__ float         g_x1[ROWS * CH];
__device__ __nv_bfloat16 g_mid[(size_t)ROWS * HID];

// ---------------- PTX helpers -------------------------------------------------

DI void cp16(uint32_t s, const void* g) {
    asm volatile("cp.async.cg.shared.global [%0], [%1], 16;\n" :: "r"(s), "l"(g));
}
DI void cp_commit() { asm volatile("cp.async.commit_group;\n"); }
template <int N> DI void cp_wait() { asm volatile("cp.async.wait_group %0;\n" :: "n"(N)); }

DI void ldsm_x4(uint32_t* r, uint32_t addr) {
    asm volatile("ldmatrix.sync.aligned.m8n8.x4.shared.b16 {%0,%1,%2,%3}, [%4];\n"
                 : "=r"(r[0]), "=r"(r[1]), "=r"(r[2]), "=r"(r[3]) : "r"(addr));
}
DI void ldsm_x4_t(uint32_t* r, uint32_t addr) {
    asm volatile("ldmatrix.sync.aligned.m8n8.x4.trans.shared.b16 {%0,%1,%2,%3}, [%4];\n"
                 : "=r"(r[0]), "=r"(r[1]), "=r"(r[2]), "=r"(r[3]) : "r"(addr));
}

DI void mma_bf16(float* c, const uint32_t* a, uint32_t b0, uint32_t b1) {
    asm volatile(
        "mma.sync.aligned.m16n8k16.row.col.f32.bf16.bf16.f32 "
        "{%0,%1,%2,%3}, {%4,%5,%6,%7}, {%8,%9}, {%0,%1,%2,%3};\n"
        : "+f"(c[0]), "+f"(c[1]), "+f"(c[2]), "+f"(c[3])
        : "r"(a[0]), "r"(a[1]), "r"(a[2]), "r"(a[3]), "r"(b0), "r"(b1));
}

DI uint32_t packbf(float lo, float hi) {
    __nv_bfloat162 t = __float22bfloat162_rn(make_float2(lo, hi));
    return *reinterpret_cast<uint32_t*>(&t);
}

// ---------------- small helper kernels ---------------------------------------

__global__ void transpose_bf16(const float* __restrict__ in,
                               __nv_bfloat16* __restrict__ out, int K, int Nc) {
    __shared__ float tile[32][33];
    int kb = blockIdx.y * 32, nb = blockIdx.x * 32;
    int tx = threadIdx.x, ty = threadIdx.y;   // block (32, 8)
#pragma unroll
    for (int i = 0; i < 4; i++)
        tile[ty + i * 8][tx] = in[(size_t)(kb + ty + i * 8) * Nc + nb + tx];
    __syncthreads();
#pragma unroll
    for (int i = 0; i < 4; i++)
        out[(size_t)(nb + ty + i * 8) * K + kb + tx] =
            __float2bfloat16(tile[tx][ty + i * 8]);
}

__global__ void ln_kernel(const float* __restrict__ x, const float* __restrict__ g,
                          const float* __restrict__ b, __nv_bfloat16* __restrict__ out) {
    int row = blockIdx.x;
    const float* xr = x + (size_t)row * CH;
    int t = threadIdx.x;
    float v0 = xr[t], v1 = xr[t + 256], v2 = xr[t + 512];
    float s  = v0 + v1 + v2;
    float s2 = v0 * v0 + v1 * v1 + v2 * v2;
#pragma unroll
    for (int o = 16; o; o >>= 1) {
        s  += __shfl_xor_sync(0xffffffffu, s,  o);
        s2 += __shfl_xor_sync(0xffffffffu, s2, o);
    }
    __shared__ float sh[16];
    int w = t >> 5, l = t & 31;
    if (l == 0) { sh[w] = s; sh[w + 8] = s2; }
    __syncthreads();
    float ts = 0.f, ts2 = 0.f;
#pragma unroll
    for (int i = 0; i < 8; i++) { ts += sh[i]; ts2 += sh[i + 8]; }
    float mu  = ts * (1.f / CH);
    float var = ts2 * (1.f / CH) - mu * mu;
    float inv = rsqrtf(var + 1e-5f);
    __nv_bfloat16* orow = out + (size_t)row * CH;
    orow[t]       = __float2bfloat16((v0 - mu) * inv * g[t]       + b[t]);
    orow[t + 256] = __float2bfloat16((v1 - mu) * inv * g[t + 256] + b[t + 256]);
    orow[t + 512] = __float2bfloat16((v2 - mu) * inv * g[t + 512] + b[t + 512]);
}

// ---------------- fused flash attention (unchanged) ---------------------------

__global__ void __launch_bounds__(256)
flash_attn(const __nv_bfloat16* __restrict__ Q, const __nv_bfloat16* __restrict__ K,
           const __nv_bfloat16* __restrict__ V, const float* __restrict__ temp,
           const float* __restrict__ lw, __nv_bfloat16* __restrict__ attn) {
    constexpr int ITERS = SEQ / 64;           // 16
    __shared__ __align__(16) uint8_t smem[49152];
    uint32_t sQ = (uint32_t)__cvta_generic_to_shared(smem);
    uint32_t sK = sQ + 16384;
    uint32_t sV = sK + 16384;

    int bh = blockIdx.y;
    int b = bh / NH, h = bh % NH;
    int qbase = blockIdx.x * 128;
    const __nv_bfloat16* qb = Q + ((size_t)bh * SEQ + qbase) * HD;
    const __nv_bfloat16* kb = K + (size_t)bh * SEQ * HD;
    const __nv_bfloat16* vb = V + (size_t)bh * SEQ * HD;

    int tid = threadIdx.x, lane = tid & 31, w = tid >> 5;
    int g = lane >> 2, ct = lane & 3;

    auto issue_kv = [&](int t, int stage) {
#pragma unroll
        for (int i = 0; i < 2; i++) {
            int idx = tid + i * 256;
            int r = idx >> 3, c = idx & 7;
            uint32_t sw = (uint32_t)((c ^ (r & 7)) << 4);
            cp16(sK + stage * 8192 + r * 128 + sw, kb + (size_t)(t * 64 + r) * HD + c * 8);
            cp16(sV + stage * 8192 + r * 128 + sw, vb + (size_t)(t * 64 + r) * HD + c * 8);
        }
    };

#pragma unroll
    for (int i = 0; i < 4; i++) {
        int idx = tid + i * 256;
        int r = idx >> 3, c = idx & 7;
        cp16(sQ + r * 128 + ((c ^ (r & 7)) << 4), qb + (size_t)r * HD + c * 8);
    }
    issue_kv(0, 0);
    cp_commit();
    issue_kv(1, 1);
    cp_commit();

    const float scale = __expf(__ldg(temp + h));
    const float lwh   = __ldg(lw + h);
    const float inv31 = 1.f / 31.f;
    int r0i = qbase + w * 16 + g, r1i = r0i + 8;
    float y0 = (float)(r0i >> 5) * inv31, x0 = (float)(r0i & 31) * inv31;
    float y1 = (float)(r1i >> 5) * inv31, x1 = (float)(r1i & 31) * inv31;
    float c0r = -0.5f * (y0 * y0 + x0 * x0);
    float c1r = -0.5f * (y1 * y1 + x1 * x1);

    float oacc[8][4];
#pragma unroll
    for (int j = 0; j < 8; j++)
#pragma unroll
        for (int q = 0; q < 4; q++) oacc[j][q] = 0.f;
    float mrun0 = -1e30f, mrun1 = -1e30f, l0 = 0.f, l1 = 0.f;

    uint32_t aq[4][4];

    for (int t = 0; t < ITERS; t++) {
        cp_wait<1>();
        __syncthreads();
        if (t == 0) {
#pragma unroll
            for (int ks = 0; ks < 4; ks++) {
                int c = ks * 2 + (lane >> 4);
                int r = w * 16 + (lane & 15);
                ldsm_x4(aq[ks], sQ + r * 128 + ((c ^ (r & 7)) << 4));
            }
        }
        int stage = t & 1;
        uint32_t kBase = sK + stage * 8192;
        uint32_t vBase = sV + stage * 8192;

        float sacc[8][4];
#pragma unroll
        for (int j = 0; j < 8; j++)
#pragma unroll
            for (int q = 0; q < 4; q++) sacc[j][q] = 0.f;
#pragma unroll
        for (int ks = 0; ks < 4; ks++) {
            int c = ks * 2 + (lane >> 4);
            uint32_t bk[4][4];
#pragma unroll
            for (int j = 0; j < 4; j++) {
                int r = j * 16 + (lane & 15);
                ldsm_x4(bk[j], kBase + r * 128 + ((c ^ (r & 7)) << 4));
            }
#pragma unroll
            for (int j = 0; j < 4; j++) {
                mma_bf16(sacc[2 * j],     aq[ks], bk[j][0], bk[j][2]);
                mma_bf16(sacc[2 * j + 1], aq[ks], bk[j][1], bk[j][3]);
            }
        }

        int colbase = t * 64;
        float mx0 = -1e30f, mx1 = -1e30f;
#pragma unroll
        for (int nt = 0; nt < 8; nt++) {
#pragma unroll
            for (int e = 0; e < 2; e++) {
                int m = colbase + nt * 8 + ct * 2 + e;
                float ym = (float)(m >> 5) * inv31, xm = (float)(m & 31) * inv31;
                float cm = -0.5f * (ym * ym + xm * xm);
                float s0 = sacc[nt][e]     * scale + lwh * (y0 * ym + x0 * xm + c0r + cm);
                float s1 = sacc[nt][2 + e] * scale + lwh * (y1 * ym + x1 * xm + c1r + cm);
                sacc[nt][e] = s0; sacc[nt][2 + e] = s1;
                mx0 = fmaxf(mx0, s0); mx1 = fmaxf(mx1, s1);
            }
        }
        mx0 = fmaxf(mx0, __shfl_xor_sync(0xffffffffu, mx0, 1));
        mx0 = fmaxf(mx0, __shfl_xor_sync(0xffffffffu, mx0, 2));
        mx1 = fmaxf(mx1, __shfl_xor_sync(0xffffffffu, mx1, 1));
        mx1 = fmaxf(mx1, __shfl_xor_sync(0xffffffffu, mx1, 2));
        float mn0 = fmaxf(mrun0, mx0), mn1 = fmaxf(mrun1, mx1);
        float al0 = __expf(mrun0 - mn0), al1 = __expf(mrun1 - mn1);
        mrun0 = mn0; mrun1 = mn1;
        l0 *= al0; l1 *= al1;
#pragma unroll
        for (int j = 0; j < 8; j++) {
            oacc[j][0] *= al0; oacc[j][1] *= al0;
            oacc[j][2] *= al1; oacc[j][3] *= al1;
        }
#pragma unroll
        for (int nt = 0; nt < 8; nt++) {
            float p0 = __expf(sacc[nt][0] - mn0);
            float p1 = __expf(sacc[nt][1] - mn0);
            float p2 = __expf(sacc[nt][2] - mn1);
            float p3 = __expf(sacc[nt][3] - mn1);
            l0 += p0 + p1; l1 += p2 + p3;
            sacc[nt][0] = p0; sacc[nt][1] = p1; sacc[nt][2] = p2; sacc[nt][3] = p3;
        }
        uint32_t ap[4][4];
#pragma unroll
        for (int ks = 0; ks < 4; ks++) {
            ap[ks][0] = packbf(sacc[2 * ks][0],     sacc[2 * ks][1]);
            ap[ks][1] = packbf(sacc[2 * ks][2],     sacc[2 * ks][3]);
            ap[ks][2] = packbf(sacc[2 * ks + 1][0], sacc[2 * ks + 1][1]);
            ap[ks][3] = packbf(sacc[2 * ks + 1][2], sacc[2 * ks + 1][3]);
        }

#pragma unroll
        for (int ks = 0; ks < 4; ks++) {
            int rr = ks * 16 + (lane & 15);
#pragma unroll
            for (int j = 0; j < 4; j++) {
                int c = 2 * j + (lane >> 4);
                uint32_t vf[4];
                ldsm_x4_t(vf, vBase + rr * 128 + ((c ^ (rr & 7)) << 4));
                mma_bf16(oacc[2 * j],     ap[ks], vf[0], vf[1]);
                mma_bf16(oacc[2 * j + 1], ap[ks], vf[2], vf[3]);
            }
        }

        __syncthreads();
        if (t + 2 < ITERS) issue_kv(t + 2, stage);
        cp_commit();
    }

    l0 += __shfl_xor_sync(0xffffffffu, l0, 1);
    l0 += __shfl_xor_sync(0xffffffffu, l0, 2);
    l1 += __shfl_xor_sync(0xffffffffu, l1, 1);
    l1 += __shfl_xor_sync(0xffffffffu, l1, 2);
    float inv0 = 1.f / l0, inv1 = 1.f / l1;
    __nv_bfloat16* o0 = attn + ((size_t)(b * SEQ + r0i)) * CH + h * HD;
    __nv_bfloat16* o1 = attn + ((size_t)(b * SEQ + r1i)) * CH + h * HD;
#pragma unroll
    for (int j = 0; j < 8; j++) {
        int col = j * 8 + ct * 2;
        __nv_bfloat162 v0 = __float22bfloat162_rn(
            make_float2(oacc[j][0] * inv0, oacc[j][1] * inv0));
        __nv_bfloat162 v1 = __float22bfloat162_rn(
            make_float2(oacc[j][2] * inv1, oacc[j][3] * inv1));
        *reinterpret_cast<__nv_bfloat162*>(o0 + col) = v0;
        *reinterpret_cast<__nv_bfloat162*>(o1 + col) = v1;
    }
}

// ---------------- bf16 GEMM: BK=64, 3-stage cp.async, 1 barrier/iter ----------
// NT: C[M,N] = A[M,K] * B[N,K]^T. 128x128x64 tiles, 256 threads (4x2 warps,
// 32x64 per warp). smem rows 128B, chunk c at (c ^ (r&7)) — same as flash.

static constexpr int G_STAGES = 3;
static constexpr int G_ASTG = 128 * 128;     // 16 KB per stage
static constexpr int G_STG  = 2 * G_ASTG;    // A+B per stage = 32 KB
static constexpr int G_DSMEM = G_STAGES * G_STG;  // 96 KB

template <class Epi>
__global__ void __launch_bounds__(256)
gemm_nt(const __nv_bfloat16* __restrict__ A, const __nv_bfloat16* __restrict__ Bm,
        int K, Epi epi) {
    extern __shared__ __align__(128) uint8_t dynsm[];
    uint32_t sBase = (uint32_t)__cvta_generic_to_shared(dynsm);

    int rowBase = blockIdx.x * 128, colBase = blockIdx.y * 128;
    int tid = threadIdx.x, lane = tid & 31, warp = tid >> 5;
    int wm = warp >> 1, wn = warp & 1;

    float acc[2][8][4];
#pragma unroll
    for (int i = 0; i < 2; i++)
#pragma unroll
        for (int j = 0; j < 8; j++)
#pragma unroll
            for (int q = 0; q < 4; q++) acc[i][j][q] = 0.f;

    const int KT = K >> 6;     // K / 64

    auto issue = [&](int kt) {
        int stage = kt % G_STAGES;
        uint32_t a0 = sBase + stage * G_STG;
        uint32_t b0 = a0 + G_ASTG;
#pragma unroll
        for (int i = 0; i < 4; i++) {
            int idx = tid + i * 256;
            int r = idx >> 3, c = idx & 7;
            uint32_t sw = (uint32_t)((c ^ (r & 7)) << 4);
            cp16(a0 + r * 128 + sw, A + (size_t)(rowBase + r) * K + kt * 64 + c * 8);
            cp16(b0 + r * 128 + sw, Bm + (size_t)(colBase + r) * K + kt * 64 + c * 8);
        }
    };

#pragma unroll
    for (int s = 0; s < G_STAGES - 1; s++) {
        if (s < KT) issue(s);
        cp_commit();
    }

    for (int kt = 0; kt < KT; kt++) {
        cp_wait<G_STAGES - 2>();
        __syncthreads();
        int nk = kt + G_STAGES - 1;
        if (nk < KT) issue(nk);      // overwrites stage read at kt-1: safe after barrier
        cp_commit();

        int stage = kt % G_STAGES;
        uint32_t aB = sBase + stage * G_STG;
        uint32_t bB = aB + G_ASTG;
#pragma unroll
        for (int kk = 0; kk < 4; kk++) {
            int c = kk * 2 + (lane >> 4);
            uint32_t afr[2][4], bfr[4][4];
#pragma unroll
            for (int mt = 0; mt < 2; mt++) {
                int r = wm * 32 + mt * 16 + (lane & 15);
                ldsm_x4(afr[mt], aB + r * 128 + ((c ^ (r & 7)) << 4));
            }
#pragma unroll
            for (int j = 0; j < 4; j++) {
                int r = wn * 64 + j * 16 + (lane & 15);
                ldsm_x4(bfr[j], bB + r * 128 + ((c ^ (r & 7)) << 4));
            }
#pragma unroll
            for (int mt = 0; mt < 2; mt++)
#pragma unroll
                for (int j = 0; j < 4; j++) {
                    mma_bf16(acc[mt][2 * j],     afr[mt], bfr[j][0], bfr[j][2]);
                    mma_bf16(acc[mt][2 * j + 1], afr[mt], bfr[j][1], bfr[j][3]);
                }
        }
    }

    int g = lane >> 2, ct = lane & 3;
#pragma unroll
    for (int mt = 0; mt < 2; mt++)
#pragma unroll
        for (int nt = 0; nt < 8; nt++) {
            int r = rowBase + wm * 32 + mt * 16 + g;
            int c = colBase + wn * 64 + nt * 8 + ct * 2;
            epi(r,     c,     acc[mt][nt][0]);
            epi(r,     c + 1, acc[mt][nt][1]);
            epi(r + 8, c,     acc[mt][nt][2]);
            epi(r + 8, c + 1, acc[mt][nt][3]);
        }
}

// ---------------- epilogues ---------------------------------------------------

struct EpiQKV {
    __nv_bfloat16 *q, *k, *v;
    DI void operator()(int r, int c, float val) const {
        int s = c / CH;
        int rem = c - s * CH;
        int h = rem >> 6, d = rem & 63;
        int b = r >> 10, n = r & 1023;
        int bh = b * NH + h;
        __nv_bfloat16 bv = __float2bfloat16(val);
        size_t idx = ((size_t)bh * SEQ + n) * HD + d;
        if (s == 0)      q[idx] = bv;
        else if (s == 1) k[idx] = bv;
        else             v[idx] = bv;
    }
};

struct EpiResid {
    const float* base;
    const float* bias;
    const float* ls;
    float* out;
    DI void operator()(int r, int c, float v) const {
        size_t i = (size_t)r * CH + c;
        out[i] = base[i] + (v + __ldg(bias + c)) * __ldg(ls + c);
    }
};

struct EpiGelu {
    const float* bias;
    __nv_bfloat16* out;
    DI void operator()(int r, int c, float v) const {
        float t = v + __ldg(bias + c);
        float gl = 0.5f * t * (1.f + erff(t * 0.70710678118654752f));
        out[(size_t)r * HID + c] = __float2bfloat16(gl);
    }
};

// ---------------- launch ------------------------------------------------------

extern "C" void kernel_launch(void* const* d_in, const int* in_sizes, int n_in,
                              void* d_out, int out_size) {
    (void)in_sizes; (void)n_in; (void)out_size;
    const float* x      = (const float*)d_in[0];
    const float* w_qkv  = (const float*)d_in[1];
    const float* w_proj = (const float*)d_in[2];
    const float* b_proj = (const float*)d_in[3];
    const float* ln1_g  = (const float*)d_in[4];
    const float* ln1_b  = (const float*)d_in[5];
    const float* ln2_g  = (const float*)d_in[6];
    const float* ln2_b  = (const float*)d_in[7];
    const float* temp   = (const float*)d_in[8];
    const float* lw     = (const float*)d_in[9];
    const float* ls1    = (const float*)d_in[10];
    const float* ls2    = (const float*)d_in[11];
    const float* w1     = (const float*)d_in[12];
    const float* b1     = (const float*)d_in[13];
    const float* w2     = (const float*)d_in[14];
    const float* b2     = (const float*)d_in[15];
    float* out = (float*)d_out;

    __nv_bfloat16 *p_h1, *p_h2, *p_wqkvT, *p_wprojT, *p_w1T, *p_w2T;
    __nv_bfloat16 *p_q, *p_k, *p_v, *p_attn, *p_mid;
    float* p_x1;
    cudaGetSymbolAddress((void**)&p_h1, g_h1);
    cudaGetSymbolAddress((void**)&p_h2, g_h2);
    cudaGetSymbolAddress((void**)&p_wqkvT, g_wqkvT);
    cudaGetSymbolAddress((void**)&p_wprojT, g_wprojT);
    cudaGetSymbolAddress((void**)&p_w1T, g_w1T);
    cudaGetSymbolAddress((void**)&p_w2T, g_w2T);
    cudaGetSymbolAddress((void**)&p_q, g_q);
    cudaGetSymbolAddress((void**)&p_k, g_k);
    cudaGetSymbolAddress((void**)&p_v, g_v);
    cudaGetSymbolAddress((void**)&p_attn, g_attn);
    cudaGetSymbolAddress((void**)&p_x1, g_x1);
    cudaGetSymbolAddress((void**)&p_mid, g_mid);

    static bool attr_done = false;
    if (!attr_done) {
        cudaFuncSetAttribute(gemm_nt<EpiQKV>,
                             cudaFuncAttributeMaxDynamicSharedMemorySize, G_DSMEM);
        cudaFuncSetAttribute(gemm_nt<EpiResid>,
                             cudaFuncAttributeMaxDynamicSharedMemorySize, G_DSMEM);
        cudaFuncSetAttribute(gemm_nt<EpiGelu>,
                             cudaFuncAttributeMaxDynamicSharedMemorySize, G_DSMEM);
        attr_done = true;
    }

    dim3 tb(32, 8);
    transpose_bf16<<<dim3((3 * CH) / 32, CH / 32), tb>>>(w_qkv, p_wqkvT, CH, 3 * CH);
    transpose_bf16<<<dim3(CH / 32, CH / 32), tb>>>(w_proj, p_wprojT, CH, CH);
    transpose_bf16<<<dim3(HID / 32, CH / 32), tb>>>(w1, p_w1T, CH, HID);
    transpose_bf16<<<dim3(CH / 32, HID / 32), tb>>>(w2, p_w2T, HID, CH);

    ln_kernel<<<ROWS, 256>>>(x, ln1_g, ln1_b, p_h1);

    {   // QKV: [8192,768] x [2304,768]^T
        EpiQKV e{p_q, p_k, p_v};
        gemm_nt<EpiQKV><<<dim3(ROWS / 128, (3 * CH) / 128), 256, G_DSMEM>>>(
            p_h1, p_wqkvT, CH, e);
    }

    flash_attn<<<dim3(SEQ / 128, BH), 256>>>(p_q, p_k, p_v, temp, lw, p_attn);

    {   // proj + residual*ls1 -> x1 (fp32)
        EpiResid e{x, b_proj, ls1, p_x1};
        gemm_nt<EpiResid><<<dim3(ROWS / 128, CH / 128), 256, G_DSMEM>>>(
            p_attn, p_wprojT, CH, e);
    }
    ln_kernel<<<ROWS, 256>>>(p_x1, ln2_g, ln2_b, p_h2);

    {   // MLP1 + gelu
        EpiGelu e{b1, p_mid};
        gemm_nt<EpiGelu><<<dim3(ROWS / 128, HID / 128), 256, G_DSMEM>>>(
            p_h2, p_w1T, CH, e);
    }
    {   // MLP2 + residual*ls2 -> out (fp32)
        EpiResid e{p_x1, b2, ls2, out};
        gemm_nt<EpiResid><<<dim3(ROWS / 128, CH / 128), 256, G_DSMEM>>>(
            p_mid, p_w2T, HID, e);
    }
}